// round 6
// baseline (speedup 1.0000x reference)
#include <cuda_runtime.h>
#include <cuda_bf16.h>
#include <cstdint>

#define Bb   2
#define Cc   64
#define Nn   2304
#define Hh   4
#define Dh   16
#define BH   (Bb*Hh)
#define MLP  256
#define NTILE 18            // Nn / 128

// flash-mma tiling
#define QT    64            // queries per block (4 warps x 16 rows)
#define KT    64            // keys per smem tile
#define KSPL  6             // key splits
#define KPB   (Nn/KSPL)     // 384 keys per block
#define NTIL  (KPB/KT)      // 6 tiles
#define SKQ   24            // sK/sQ row stride (bf16) - conflict free
#define SVT   72            // sVt row stride (bf16) - conflict free

typedef unsigned long long u64;

// ---------------- scratch (device globals; no allocation) ----------------
__device__ float g_xt [Bb*Nn*Cc];
__device__ float g_y1 [BH*Nn*Dh];
__device__ float g_y2 [BH*Nn*Dh];
__device__ float g_x1 [BH*Nn*Dh];
__device__ float g_x2 [BH*Nn*Dh];
__device__ float g_secp[BH*NTILE*256];
__device__ float g_secm[BH*256];
__device__ float g_po [KSPL*BH*Nn*16];   // unnormalized attention partials
__device__ float g_pl [KSPL*BH*Nn];      // partial row sums

// ---------------- helpers ----------------
__device__ __forceinline__ float ex2a(float x) {
    float r; asm("ex2.approx.f32 %0, %1;" : "=f"(r) : "f"(x)); return r;
}
__device__ __forceinline__ uint32_t cvt_bf2(float hi, float lo) {
    uint32_t r; asm("cvt.rn.bf16x2.f32 %0, %1, %2;" : "=r"(r) : "f"(hi), "f"(lo)); return r;
}
__device__ __forceinline__ void mma16816(float d[4],
    uint32_t a0, uint32_t a1, uint32_t a2, uint32_t a3,
    uint32_t b0, uint32_t b1)
{
    asm volatile("mma.sync.aligned.m16n8k16.row.col.f32.bf16.bf16.f32 "
        "{%0,%1,%2,%3}, {%4,%5,%6,%7}, {%8,%9}, {%0,%1,%2,%3};"
        : "+f"(d[0]), "+f"(d[1]), "+f"(d[2]), "+f"(d[3])
        : "r"(a0), "r"(a1), "r"(a2), "r"(a3), "r"(b0), "r"(b1));
}
__device__ __forceinline__ u64 fma2(u64 a, u64 b, u64 c) {
    u64 d; asm("fma.rn.f32x2 %0, %1, %2, %3;" : "=l"(d) : "l"(a), "l"(b), "l"(c)); return d;
}
__device__ __forceinline__ float2 unpk(u64 v) {
    float2 r; asm("mov.b64 {%0,%1}, %2;" : "=f"(r.x), "=f"(r.y) : "l"(v)); return r;
}
__device__ __forceinline__ u64 pk(float lo, float hi) {
    u64 v; asm("mov.b64 %0, {%1,%2};" : "=l"(v) : "f"(lo), "f"(hi)); return v;
}

// ---------------- K1: transpose + LayerNorm + 4 projections (8 rows/block) ----------------
__global__ __launch_bounds__(64) void k_ln_proj(
    const float* __restrict__ x, const float* __restrict__ y,
    const float* __restrict__ g, const float* __restrict__ be,
    const float* __restrict__ wsa1, const float* __restrict__ wsa2,
    const float* __restrict__ wse1, const float* __restrict__ wse2)
{
    const int t = threadIdx.x;
    const int row0 = blockIdx.x * 8;
    const int b = row0 / Nn;
    const int n0 = row0 - b*Nn;
    __shared__ u64 sxnp[4][64], synp[4][64];
    __shared__ float sred[2][32];

    float xv[8], yv[8];
#pragma unroll
    for (int r = 0; r < 8; r++) {
        xv[r] = x[((size_t)b*Cc + t)*Nn + n0 + r];
        yv[r] = y[((size_t)b*Cc + t)*Nn + n0 + r];
        g_xt[(size_t)(row0+r)*Cc + t] = xv[r];
    }
    const int wid = t >> 5, lane = t & 31;
#pragma unroll
    for (int r = 0; r < 8; r++) {
        float a = xv[r], a2 = a*a, bb = yv[r], b2v = bb*bb;
#pragma unroll
        for (int o = 16; o > 0; o >>= 1) {
            a   += __shfl_xor_sync(0xffffffffu, a,   o);
            a2  += __shfl_xor_sync(0xffffffffu, a2,  o);
            bb  += __shfl_xor_sync(0xffffffffu, bb,  o);
            b2v += __shfl_xor_sync(0xffffffffu, b2v, o);
        }
        if (lane == 0) {
            sred[wid][r*4+0] = a;  sred[wid][r*4+1] = a2;
            sred[wid][r*4+2] = bb; sred[wid][r*4+3] = b2v;
        }
    }
    __syncthreads();
    const float gt = g[t], bet = be[t];
    float xnv[8], ynv[8];
#pragma unroll
    for (int r = 0; r < 8; r++) {
        float sx  = sred[0][r*4+0] + sred[1][r*4+0];
        float sx2 = sred[0][r*4+1] + sred[1][r*4+1];
        float sy  = sred[0][r*4+2] + sred[1][r*4+2];
        float sy2 = sred[0][r*4+3] + sred[1][r*4+3];
        float mx = sx*(1.f/64.f), vx = sx2*(1.f/64.f) - mx*mx;
        float my = sy*(1.f/64.f), vy = sy2*(1.f/64.f) - my*my;
        float rx = rsqrtf(vx + 1e-5f), ry = rsqrtf(vy + 1e-5f);
        xnv[r] = (xv[r]-mx)*rx*gt + bet;
        ynv[r] = (yv[r]-my)*ry*gt + bet;
    }
#pragma unroll
    for (int p = 0; p < 4; p++) {
        sxnp[p][t] = pk(xnv[2*p], xnv[2*p+1]);
        synp[p][t] = pk(ynv[2*p], ynv[2*p+1]);
    }
    __syncthreads();

    u64 a1[4] = {0,0,0,0}, a2a[4] = {0,0,0,0}, a3[4] = {0,0,0,0}, a4[4] = {0,0,0,0};
#pragma unroll 4
    for (int c = 0; c < 64; c++) {
        u64 w1p = pk(wsa1[c*64+t], wsa1[c*64+t]);
        u64 w2p = pk(wsa2[c*64+t], wsa2[c*64+t]);
        u64 w3p = pk(wse1[c*64+t], wse1[c*64+t]);
        u64 w4p = pk(wse2[c*64+t], wse2[c*64+t]);
#pragma unroll
        for (int p = 0; p < 4; p++) {
            u64 yc = synp[p][c], xc = sxnp[p][c];
            a1[p]  = fma2(yc, w1p, a1[p]);
            a2a[p] = fma2(yc, w2p, a2a[p]);
            a3[p]  = fma2(xc, w3p, a3[p]);
            a4[p]  = fma2(xc, w4p, a4[p]);
        }
    }
    const int h = t >> 4, d = t & 15;
#pragma unroll
    for (int p = 0; p < 4; p++) {
        size_t o0 = ((size_t)(b*Hh + h)*Nn + n0 + 2*p)*Dh + d;
        size_t o1 = o0 + Dh;
        float2 u1 = unpk(a1[p]),  u2 = unpk(a2a[p]);
        float2 u3 = unpk(a3[p]),  u4 = unpk(a4[p]);
        g_y1[o0] = u1.x; g_y1[o1] = u1.y;
        g_y2[o0] = u2.x; g_y2[o1] = u2.y;
        g_x1[o0] = u3.x; g_x1[o1] = u3.y;
        g_x2[o0] = u4.x; g_x2[o1] = u4.y;
    }
}

// ---------------- K2a: channel-attn logits, partial over n-tiles ----------------
__global__ __launch_bounds__(256) void k_secm_part()
{
    const int bh = blockIdx.y, nb = blockIdx.x;
    const int t = threadIdx.x, i = t >> 4, j = t & 15;
    const float* __restrict__ x1 = g_x1 + (size_t)bh*Nn*Dh;
    const float* __restrict__ x2 = g_x2 + (size_t)bh*Nn*Dh;
    const int n0 = nb * 128;
    float s = 0.f;
#pragma unroll 4
    for (int n = n0; n < n0 + 128; n++)
        s = fmaf(x1[n*16 + i], x2[n*16 + j], s);
    g_secp[((size_t)bh*NTILE + nb)*256 + t] = s;
}

// ---------------- K2b: reduce partials + softmax (16x16 per bh) ----------------
__global__ __launch_bounds__(256) void k_secm_soft()
{
    const int bh = blockIdx.x;
    const int t = threadIdx.x, i = t >> 4;
    float s = 0.f;
#pragma unroll
    for (int k = 0; k < NTILE; k++)
        s += g_secp[((size_t)bh*NTILE + k)*256 + t];
    s *= (0.25f / 144.0f);
    __shared__ float sm[16][16], se[16][16];
    sm[i][t & 15] = s;
    __syncthreads();
    float rmax = -1e30f;
#pragma unroll
    for (int k = 0; k < 16; k++) rmax = fmaxf(rmax, sm[i][k]);
    float e = __expf(s - rmax);
    se[i][t & 15] = e;
    __syncthreads();
    float rs = 0.f;
#pragma unroll
    for (int k = 0; k < 16; k++) rs += se[i][k];
    g_secm[bh*256 + t] = e / rs;
}

// ---------------- K3: flash attention via bf16 mma.sync, double-buffered ----------------
// grid (Nn/QT=36, BH, KSPL), 128 threads = 4 warps, 16 query rows per warp.
__global__ __launch_bounds__(128) void k_flash_mma()
{
    const int qt = blockIdx.x, bh = blockIdx.y, ks = blockIdx.z;
    const int t = threadIdx.x, wid = t >> 5, lane = t & 31;
    const int g = lane >> 2, tg = lane & 3;

    __shared__ __align__(16) __nv_bfloat16 sQ [QT*SKQ];
    __shared__ __align__(16) __nv_bfloat16 sK [2][KT*SKQ];
    __shared__ __align__(16) __nv_bfloat16 sVt[2][16*SVT];

    const float* __restrict__ Qb = g_y1 + (size_t)bh*Nn*Dh;
    const float* __restrict__ Kb = g_y2 + (size_t)bh*Nn*Dh;
    const float* __restrict__ Vb = g_x1 + (size_t)bh*Nn*Dh;

    // Q tile -> bf16 smem (rows stride SKQ)
    {
        const float4* src = (const float4*)(Qb + (size_t)qt*QT*16);
#pragma unroll
        for (int i = t; i < QT*4; i += 128) {
            float4 v = src[i];
            int key = i >> 2, dq = (i & 3) * 4;
            __nv_bfloat16* d = sQ + key*SKQ + dq;
            d[0] = __float2bfloat16(v.x); d[1] = __float2bfloat16(v.y);
            d[2] = __float2bfloat16(v.z); d[3] = __float2bfloat16(v.w);
        }
    }

    // preload tile 0 into buffer 0
    {
        const int key0 = ks*KPB;
        const float4* srcK = (const float4*)(Kb + (size_t)key0*16);
        const float4* srcV = (const float4*)(Vb + (size_t)key0*16);
#pragma unroll
        for (int i = t; i < KT*4; i += 128) {
            float4 kv = srcK[i];
            int key = i >> 2, dq = (i & 3) * 4;
            __nv_bfloat16* d = sK[0] + key*SKQ + dq;
            d[0] = __float2bfloat16(kv.x); d[1] = __float2bfloat16(kv.y);
            d[2] = __float2bfloat16(kv.z); d[3] = __float2bfloat16(kv.w);
            float4 vv = srcV[i];
            sVt[0][(dq+0)*SVT + key] = __float2bfloat16(vv.x);
            sVt[0][(dq+1)*SVT + key] = __float2bfloat16(vv.y);
            sVt[0][(dq+2)*SVT + key] = __float2bfloat16(vv.z);
            sVt[0][(dq+3)*SVT + key] = __float2bfloat16(vv.w);
        }
    }
    __syncthreads();

    // per-warp Q A-fragment (rows wid*16 .. +15), reused all tiles
    const int qr = wid * 16;
    uint32_t qa0 = *(const uint32_t*)(sQ + (qr+g  )*SKQ + 2*tg);
    uint32_t qa1 = *(const uint32_t*)(sQ + (qr+g+8)*SKQ + 2*tg);
    uint32_t qa2 = *(const uint32_t*)(sQ + (qr+g  )*SKQ + 2*tg + 8);
    uint32_t qa3 = *(const uint32_t*)(sQ + (qr+g+8)*SKQ + 2*tg + 8);

    float o[2][4] = {{0,0,0,0},{0,0,0,0}};
    float lsum_lo = 0.f, lsum_hi = 0.f;
    const float SC = 0.25f * 1.4426950408889634f;   // scale * log2(e)

    for (int kt = 0; kt < NTIL; kt++) {
        const int cur = kt & 1;
        const bool more = (kt + 1 < NTIL);

        // prefetch next tile to registers
        float4 kreg[2], vreg[2];
        if (more) {
            const int key0 = ks*KPB + (kt+1)*KT;
            const float4* srcK = (const float4*)(Kb + (size_t)key0*16);
            const float4* srcV = (const float4*)(Vb + (size_t)key0*16);
#pragma unroll
            for (int u = 0; u < 2; u++) {
                kreg[u] = srcK[t + u*128];
                vreg[u] = srcV[t + u*128];
            }
        }

        const __nv_bfloat16* kb_s = sK[cur];
        const __nv_bfloat16* vb_s = sVt[cur];

        // S = Q K^T  (16 x 64), 8 n-tiles of 8 keys
        float s[8][4];
        uint32_t p[8][2];
#pragma unroll
        for (int n = 0; n < 8; n++) {
            s[n][0] = s[n][1] = s[n][2] = s[n][3] = 0.f;
            uint32_t b0 = *(const uint32_t*)(kb_s + (n*8+g)*SKQ + 2*tg);
            uint32_t b1 = *(const uint32_t*)(kb_s + (n*8+g)*SKQ + 2*tg + 8);
            mma16816(s[n], qa0, qa1, qa2, qa3, b0, b1);
        }
        // exp (max-free: logits tiny by construction) + pack to bf16 P frags
#pragma unroll
        for (int n = 0; n < 8; n++) {
            float e0 = ex2a(s[n][0]*SC), e1 = ex2a(s[n][1]*SC);
            float e2 = ex2a(s[n][2]*SC), e3 = ex2a(s[n][3]*SC);
            lsum_lo += e0 + e1;  lsum_hi += e2 + e3;
            p[n][0] = cvt_bf2(e1, e0);   // low = col 2tg
            p[n][1] = cvt_bf2(e3, e2);
        }
        // O += P V  (4 k-tiles of 16 keys, 2 n-tiles of 8 dims)
#pragma unroll
        for (int kk = 0; kk < 4; kk++) {
            uint32_t a0 = p[2*kk][0],   a1 = p[2*kk][1];
            uint32_t a2 = p[2*kk+1][0], a3 = p[2*kk+1][1];
#pragma unroll
            for (int n = 0; n < 2; n++) {
                uint32_t b0 = *(const uint32_t*)(vb_s + (n*8+g)*SVT + kk*16 + 2*tg);
                uint32_t b1 = *(const uint32_t*)(vb_s + (n*8+g)*SVT + kk*16 + 2*tg + 8);
                mma16816(o[n], a0, a1, a2, a3, b0, b1);
            }
        }

        // store prefetched tile into the other buffer
        if (more) {
            const int nxt = cur ^ 1;
#pragma unroll
            for (int u = 0; u < 2; u++) {
                int i = t + u*128;
                int key = i >> 2, dq = (i & 3) * 4;
                __nv_bfloat16* d = sK[nxt] + key*SKQ + dq;
                d[0] = __float2bfloat16(kreg[u].x); d[1] = __float2bfloat16(kreg[u].y);
                d[2] = __float2bfloat16(kreg[u].z); d[3] = __float2bfloat16(kreg[u].w);
                sVt[nxt][(dq+0)*SVT + key] = __float2bfloat16(vreg[u].x);
                sVt[nxt][(dq+1)*SVT + key] = __float2bfloat16(vreg[u].y);
                sVt[nxt][(dq+2)*SVT + key] = __float2bfloat16(vreg[u].z);
                sVt[nxt][(dq+3)*SVT + key] = __float2bfloat16(vreg[u].w);
            }
            __syncthreads();
        }
    }

    // reduce row sums across the 4 lanes of each group
    lsum_lo += __shfl_xor_sync(0xffffffffu, lsum_lo, 1);
    lsum_lo += __shfl_xor_sync(0xffffffffu, lsum_lo, 2);
    lsum_hi += __shfl_xor_sync(0xffffffffu, lsum_hi, 1);
    lsum_hi += __shfl_xor_sync(0xffffffffu, lsum_hi, 2);

    // write partials
    const int q_lo = qt*QT + qr + g;
    const int q_hi = q_lo + 8;
    float* po = g_po + ((size_t)(ks*BH + bh)*Nn)*16;
#pragma unroll
    for (int n = 0; n < 2; n++) {
        po[(size_t)q_lo*16 + n*8 + 2*tg    ] = o[n][0];
        po[(size_t)q_lo*16 + n*8 + 2*tg + 1] = o[n][1];
        po[(size_t)q_hi*16 + n*8 + 2*tg    ] = o[n][2];
        po[(size_t)q_hi*16 + n*8 + 2*tg + 1] = o[n][3];
    }
    if (tg == 0) {
        g_pl[(size_t)(ks*BH + bh)*Nn + q_lo] = lsum_lo;
        g_pl[(size_t)(ks*BH + bh)*Nn + q_hi] = lsum_hi;
    }
}

// ---------------- K4: combine + epilogue + out-proj + LN2 + MLP (8 rows/block) ----------------
__device__ __forceinline__ float leaky(float h) { return h > 0.f ? h : 0.01f * h; }

__global__ __launch_bounds__(64) void k_tail(
    const float* __restrict__ wout, const float* __restrict__ bout,
    const float* __restrict__ g2,   const float* __restrict__ be2,
    const float* __restrict__ w1,   const float* __restrict__ b1,
    const float* __restrict__ w2,   const float* __restrict__ b2,
    float* __restrict__ out)
{
    const int t = threadIdx.x;
    const int row0 = blockIdx.x * 8;
    const int b = row0 / Nn;
    const int n0 = row0 - b*Nn;
    const int h = t >> 4, d = t & 15;
    const int bh = b*Hh + h;

    __shared__ float ssec[4][256];
    __shared__ float sq[8][64];
    __shared__ float sinvl[8][4];
    __shared__ u64 sop[4][64];   // attn-out packed row pairs
    __shared__ u64 snp[4][64];
    __shared__ u64 shp[4][256];
    __shared__ float sred[2][16];

    // channel softmax maps for the 4 heads of this batch
#pragma unroll
    for (int k = 0; k < 16; k++) {
        int idx = k*64 + t;
        ssec[idx >> 8][idx & 255] = g_secm[(b*Hh + (idx >> 8))*256 + (idx & 255)];
    }
    // Q rows (y1) for the 8 rows
#pragma unroll
    for (int r = 0; r < 8; r++)
        sq[r][t] = g_y1[((size_t)bh*Nn + n0 + r)*16 + d];
    // inverse row sums
    if (t < 32) {
        int r = t >> 2, hh = t & 3;
        float l = 0.f;
#pragma unroll
        for (int ks = 0; ks < KSPL; ks++)
            l += g_pl[(size_t)(ks*BH + b*Hh + hh)*Nn + n0 + r];
        sinvl[r][hh] = 1.0f / l;
    }
    __syncthreads();

    // combine po splits + channel-map epilogue -> attn output channel t per row
    float soval[8];
#pragma unroll
    for (int r = 0; r < 8; r++) {
        float pv = 0.f;
#pragma unroll
        for (int ks = 0; ks < KSPL; ks++)
            pv += g_po[((size_t)(ks*BH + bh)*Nn + n0 + r)*16 + d];
        float o2 = 0.f;
#pragma unroll
        for (int i = 0; i < 16; i++)
            o2 = fmaf(sq[r][h*16 + i], ssec[h][i*16 + d], o2);
        soval[r] = pv * sinvl[r][h] * o2;
    }
#pragma unroll
    for (int p = 0; p < 4; p++)
        sop[p][t] = pk(soval[2*p], soval[2*p+1]);
    __syncthreads();

    u64 ac[4] = {0ull, 0ull, 0ull, 0ull};
#pragma unroll 4
    for (int c = 0; c < 64; c++) {
        float w = wout[c*64 + t];
        u64 ww = pk(w, w);
#pragma unroll
        for (int p = 0; p < 4; p++)
            ac[p] = fma2(ww, sop[p][c], ac[p]);
    }
    const float bo = bout[t];
    float x2v[8];
#pragma unroll
    for (int p = 0; p < 4; p++) {
        float2 u = unpk(ac[p]);
        x2v[2*p]   = g_xt[(size_t)(row0+2*p  )*64 + t] + u.x + bo;
        x2v[2*p+1] = g_xt[(size_t)(row0+2*p+1)*64 + t] + u.y + bo;
    }

    const int wid = t >> 5, lane = t & 31;
#pragma unroll
    for (int r = 0; r < 8; r++) {
        float a = x2v[r], a2 = a*a;
#pragma unroll
        for (int o = 16; o > 0; o >>= 1) {
            a  += __shfl_xor_sync(0xffffffffu, a,  o);
            a2 += __shfl_xor_sync(0xffffffffu, a2, o);
        }
        if (lane == 0) { sred[wid][r*2] = a; sred[wid][r*2+1] = a2; }
    }
    __syncthreads();
    const float g2t = g2[t], be2t = be2[t];
    float snv[8];
#pragma unroll
    for (int r = 0; r < 8; r++) {
        float sxx = sred[0][r*2] + sred[1][r*2];
        float sq2 = sred[0][r*2+1] + sred[1][r*2+1];
        float m = sxx*(1.f/64.f), v = sq2*(1.f/64.f) - m*m;
        snv[r] = (x2v[r]-m)*rsqrtf(v + 1e-5f)*g2t + be2t;
    }
#pragma unroll
    for (int p = 0; p < 4; p++)
        snp[p][t] = pk(snv[2*p], snv[2*p+1]);
    __syncthreads();

    // MLP layer 1 (64 -> 256), 4 output chunks x 4 row-pairs
    u64 hh[4][4];
#pragma unroll
    for (int o2 = 0; o2 < 4; o2++) {
        float bb = b1[t + o2*64];
#pragma unroll
        for (int p = 0; p < 4; p++) hh[o2][p] = pk(bb, bb);
    }
#pragma unroll 2
    for (int c = 0; c < 64; c++) {
        u64 xp[4];
#pragma unroll
        for (int p = 0; p < 4; p++) xp[p] = snp[p][c];
#pragma unroll
        for (int o2 = 0; o2 < 4; o2++) {
            float w = w1[c*256 + t + o2*64];
            u64 ww = pk(w, w);
#pragma unroll
            for (int p = 0; p < 4; p++)
                hh[o2][p] = fma2(ww, xp[p], hh[o2][p]);
        }
    }
#pragma unroll
    for (int o2 = 0; o2 < 4; o2++) {
#pragma unroll
        for (int p = 0; p < 4; p++) {
            float2 u = unpk(hh[o2][p]);
            shp[p][t + o2*64] = pk(leaky(u.x), leaky(u.y));
        }
    }
    __syncthreads();

    // MLP layer 2 (256 -> 64)
    u64 f[4] = {0ull, 0ull, 0ull, 0ull};
#pragma unroll 4
    for (int j = 0; j < 256; j++) {
        float w = w2[j*64 + t];
        u64 ww = pk(w, w);
#pragma unroll
        for (int p = 0; p < 4; p++)
            f[p] = fma2(ww, shp[p][j], f[p]);
    }
    const float b2t = b2[t];
#pragma unroll
    for (int p = 0; p < 4; p++) {
        float2 u = unpk(f[p]);
        out[((size_t)b*Cc + t)*Nn + n0 + 2*p    ] = x2v[2*p]   + u.x + b2t;
        out[((size_t)b*Cc + t)*Nn + n0 + 2*p + 1] = x2v[2*p+1] + u.y + b2t;
    }
}

// ---------------- launch ----------------
extern "C" void kernel_launch(void* const* d_in, const int* in_sizes, int n_in,
                              void* d_out, int out_size)
{
    (void)in_sizes; (void)n_in; (void)out_size;
    const float* x    = (const float*)d_in[0];
    const float* y    = (const float*)d_in[1];
    const float* ln1g = (const float*)d_in[2];
    const float* ln1b = (const float*)d_in[3];
    const float* wsa1 = (const float*)d_in[4];
    const float* wsa2 = (const float*)d_in[5];
    const float* wse1 = (const float*)d_in[6];
    const float* wse2 = (const float*)d_in[7];
    const float* wout = (const float*)d_in[8];
    const float* bout = (const float*)d_in[9];
    const float* ln2g = (const float*)d_in[10];
    const float* ln2b = (const float*)d_in[11];
    const float* w1   = (const float*)d_in[12];
    const float* b1   = (const float*)d_in[13];
    const float* w2   = (const float*)d_in[14];
    const float* b2   = (const float*)d_in[15];
    float* out = (float*)d_out;

    k_ln_proj<<<Bb*Nn/8, 64>>>(x, y, ln1g, ln1b, wsa1, wsa2, wse1, wse2);
    dim3 gsec(NTILE, BH);
    k_secm_part<<<gsec, 256>>>();
    k_secm_soft<<<BH, 256>>>();
    dim3 gfl(Nn/QT, BH, KSPL);
    k_flash_mma<<<gfl, 128>>>();
    k_tail<<<Bb*Nn/8, 64>>>(wout, bout, ln2g, ln2b, w1, b1, w2, b2, out);
}

// round 7
// speedup vs baseline: 1.0707x; 1.0707x over previous
#include <cuda_runtime.h>
#include <cuda_bf16.h>
#include <cstdint>

#define Bb   2
#define Cc   64
#define Nn   2304
#define Hh   4
#define Dh   16
#define BH   (Bb*Hh)
#define MLP  256
#define NTILE 18            // Nn / 128

// flash-mma tiling
#define QT    64            // queries per block (4 warps x 16 rows)
#define KT    64            // keys per smem tile
#define KSPL  4             // key splits
#define KPB   (Nn/KSPL)     // 576 keys per block
#define NTIL  (KPB/KT)      // 9 tiles
#define SKQ   24            // sK/sQ row stride (bf16) - conflict free
#define SVT   72            // sVt row stride (bf16) - conflict free

typedef unsigned long long u64;

// ---------------- scratch (device globals; no allocation) ----------------
__device__ float g_xt [Bb*Nn*Cc];
__device__ float g_y1 [BH*Nn*Dh];
__device__ float g_y2 [BH*Nn*Dh];
__device__ float g_x1 [BH*Nn*Dh];
__device__ float g_x2 [BH*Nn*Dh];
__device__ float g_secp[BH*NTILE*256];
__device__ float g_secm[BH*256];
__device__ float g_po [KSPL*BH*Nn*16];   // unnormalized attention partials
__device__ float g_pl [KSPL*BH*Nn];      // partial row sums

// ---------------- helpers ----------------
__device__ __forceinline__ float ex2a(float x) {
    float r; asm("ex2.approx.f32 %0, %1;" : "=f"(r) : "f"(x)); return r;
}
__device__ __forceinline__ uint32_t cvt_bf2(float hi, float lo) {
    uint32_t r; asm("cvt.rn.bf16x2.f32 %0, %1, %2;" : "=r"(r) : "f"(hi), "f"(lo)); return r;
}
__device__ __forceinline__ void mma16816(float d[4],
    uint32_t a0, uint32_t a1, uint32_t a2, uint32_t a3,
    uint32_t b0, uint32_t b1)
{
    asm volatile("mma.sync.aligned.m16n8k16.row.col.f32.bf16.bf16.f32 "
        "{%0,%1,%2,%3}, {%4,%5,%6,%7}, {%8,%9}, {%0,%1,%2,%3};"
        : "+f"(d[0]), "+f"(d[1]), "+f"(d[2]), "+f"(d[3])
        : "r"(a0), "r"(a1), "r"(a2), "r"(a3), "r"(b0), "r"(b1));
}
__device__ __forceinline__ u64 fma2(u64 a, u64 b, u64 c) {
    u64 d; asm("fma.rn.f32x2 %0, %1, %2, %3;" : "=l"(d) : "l"(a), "l"(b), "l"(c)); return d;
}
__device__ __forceinline__ float2 unpk(u64 v) {
    float2 r; asm("mov.b64 {%0,%1}, %2;" : "=f"(r.x), "=f"(r.y) : "l"(v)); return r;
}
__device__ __forceinline__ u64 pk(float lo, float hi) {
    u64 v; asm("mov.b64 %0, {%1,%2};" : "=l"(v) : "f"(lo), "f"(hi)); return v;
}

// ---------------- K1: transpose + LN + 4 projections (8 rows, 128 thr) ----------------
// Half h2 = t>>6 owns rows 4*h2..4*h2+3 (pairs 2*h2, 2*h2+1). Weights read once
// per block serve 8 rows.
__global__ __launch_bounds__(128) void k_ln_proj(
    const float* __restrict__ x, const float* __restrict__ y,
    const float* __restrict__ g, const float* __restrict__ be,
    const float* __restrict__ wsa1, const float* __restrict__ wsa2,
    const float* __restrict__ wse1, const float* __restrict__ wse2)
{
    const int t = threadIdx.x;
    const int c = t & 63, h2 = t >> 6;
    const int row0 = blockIdx.x * 8;
    const int b = row0 / Nn;
    const int n0 = row0 - b*Nn;
    __shared__ u64 sxnp[4][64], synp[4][64];
    __shared__ float sred[4][16];

    float xv[4], yv[4];
#pragma unroll
    for (int k = 0; k < 4; k++) {
        int nn = n0 + 4*h2 + k;
        xv[k] = x[((size_t)b*Cc + c)*Nn + nn];
        yv[k] = y[((size_t)b*Cc + c)*Nn + nn];
        g_xt[(size_t)(row0 + 4*h2 + k)*Cc + c] = xv[k];
    }
    const int wid = t >> 5, lane = t & 31;
#pragma unroll
    for (int k = 0; k < 4; k++) {
        float a = xv[k], a2 = a*a, bb = yv[k], b2v = bb*bb;
#pragma unroll
        for (int o = 16; o > 0; o >>= 1) {
            a   += __shfl_xor_sync(0xffffffffu, a,   o);
            a2  += __shfl_xor_sync(0xffffffffu, a2,  o);
            bb  += __shfl_xor_sync(0xffffffffu, bb,  o);
            b2v += __shfl_xor_sync(0xffffffffu, b2v, o);
        }
        if (lane == 0) {
            sred[wid][k*4+0] = a;  sred[wid][k*4+1] = a2;
            sred[wid][k*4+2] = bb; sred[wid][k*4+3] = b2v;
        }
    }
    __syncthreads();
    const float gt = g[c], bet = be[c];
    float xnv[4], ynv[4];
    const int w0i = 2*h2, w1i = 2*h2 + 1;
#pragma unroll
    for (int k = 0; k < 4; k++) {
        float sx  = sred[w0i][k*4+0] + sred[w1i][k*4+0];
        float sx2 = sred[w0i][k*4+1] + sred[w1i][k*4+1];
        float sy  = sred[w0i][k*4+2] + sred[w1i][k*4+2];
        float sy2 = sred[w0i][k*4+3] + sred[w1i][k*4+3];
        float mx = sx*(1.f/64.f), vx = sx2*(1.f/64.f) - mx*mx;
        float my = sy*(1.f/64.f), vy = sy2*(1.f/64.f) - my*my;
        float rx = rsqrtf(vx + 1e-5f), ry = rsqrtf(vy + 1e-5f);
        xnv[k] = (xv[k]-mx)*rx*gt + bet;
        ynv[k] = (yv[k]-my)*ry*gt + bet;
    }
    sxnp[2*h2  ][c] = pk(xnv[0], xnv[1]);
    sxnp[2*h2+1][c] = pk(xnv[2], xnv[3]);
    synp[2*h2  ][c] = pk(ynv[0], ynv[1]);
    synp[2*h2+1][c] = pk(ynv[2], ynv[3]);
    __syncthreads();

    // projections for own 2 row-pairs; weight LDGs broadcast across halves
    u64 a1[2] = {0,0}, a2a[2] = {0,0}, a3[2] = {0,0}, a4[2] = {0,0};
#pragma unroll 4
    for (int c2 = 0; c2 < 64; c2++) {
        float w1v = wsa1[c2*64+c], w2v = wsa2[c2*64+c];
        float w3v = wse1[c2*64+c], w4v = wse2[c2*64+c];
        u64 w1p = pk(w1v, w1v), w2p = pk(w2v, w2v);
        u64 w3p = pk(w3v, w3v), w4p = pk(w4v, w4v);
#pragma unroll
        for (int pi = 0; pi < 2; pi++) {
            u64 yc = synp[2*h2+pi][c2], xc = sxnp[2*h2+pi][c2];
            a1[pi]  = fma2(yc, w1p, a1[pi]);
            a2a[pi] = fma2(yc, w2p, a2a[pi]);
            a3[pi]  = fma2(xc, w3p, a3[pi]);
            a4[pi]  = fma2(xc, w4p, a4[pi]);
        }
    }
    const int h = c >> 4, d = c & 15;
#pragma unroll
    for (int pi = 0; pi < 2; pi++) {
        size_t o0 = ((size_t)(b*Hh + h)*Nn + n0 + 4*h2 + 2*pi)*Dh + d;
        size_t o1 = o0 + Dh;
        float2 u1 = unpk(a1[pi]),  u2 = unpk(a2a[pi]);
        float2 u3 = unpk(a3[pi]),  u4 = unpk(a4[pi]);
        g_y1[o0] = u1.x; g_y1[o1] = u1.y;
        g_y2[o0] = u2.x; g_y2[o1] = u2.y;
        g_x1[o0] = u3.x; g_x1[o1] = u3.y;
        g_x2[o0] = u4.x; g_x2[o1] = u4.y;
    }
}

// ---------------- K2a: channel-attn logits, partial over n-tiles ----------------
__global__ __launch_bounds__(256) void k_secm_part()
{
    const int bh = blockIdx.y, nb = blockIdx.x;
    const int t = threadIdx.x, i = t >> 4, j = t & 15;
    const float* __restrict__ x1 = g_x1 + (size_t)bh*Nn*Dh;
    const float* __restrict__ x2 = g_x2 + (size_t)bh*Nn*Dh;
    const int n0 = nb * 128;
    float s = 0.f;
#pragma unroll 4
    for (int n = n0; n < n0 + 128; n++)
        s = fmaf(x1[n*16 + i], x2[n*16 + j], s);
    g_secp[((size_t)bh*NTILE + nb)*256 + t] = s;
}

// ---------------- K2b: reduce partials + softmax (16x16 per bh) ----------------
__global__ __launch_bounds__(256) void k_secm_soft()
{
    const int bh = blockIdx.x;
    const int t = threadIdx.x, i = t >> 4;
    float s = 0.f;
#pragma unroll
    for (int k = 0; k < NTILE; k++)
        s += g_secp[((size_t)bh*NTILE + k)*256 + t];
    s *= (0.25f / 144.0f);
    __shared__ float sm[16][16], se[16][16];
    sm[i][t & 15] = s;
    __syncthreads();
    float rmax = -1e30f;
#pragma unroll
    for (int k = 0; k < 16; k++) rmax = fmaxf(rmax, sm[i][k]);
    float e = __expf(s - rmax);
    se[i][t & 15] = e;
    __syncthreads();
    float rs = 0.f;
#pragma unroll
    for (int k = 0; k < 16; k++) rs += se[i][k];
    g_secm[bh*256 + t] = e / rs;
}

// ---------------- K3: flash attention via bf16 mma.sync, double-buffered ----------------
__global__ __launch_bounds__(128) void k_flash_mma()
{
    const int qt = blockIdx.x, bh = blockIdx.y, ks = blockIdx.z;
    const int t = threadIdx.x, wid = t >> 5, lane = t & 31;
    const int g = lane >> 2, tg = lane & 3;

    __shared__ __align__(16) __nv_bfloat16 sQ [QT*SKQ];
    __shared__ __align__(16) __nv_bfloat16 sK [2][KT*SKQ];
    __shared__ __align__(16) __nv_bfloat16 sVt[2][16*SVT];

    const float* __restrict__ Qb = g_y1 + (size_t)bh*Nn*Dh;
    const float* __restrict__ Kb = g_y2 + (size_t)bh*Nn*Dh;
    const float* __restrict__ Vb = g_x1 + (size_t)bh*Nn*Dh;

    {
        const float4* src = (const float4*)(Qb + (size_t)qt*QT*16);
#pragma unroll
        for (int i = t; i < QT*4; i += 128) {
            float4 v = src[i];
            int key = i >> 2, dq = (i & 3) * 4;
            __nv_bfloat16* d = sQ + key*SKQ + dq;
            d[0] = __float2bfloat16(v.x); d[1] = __float2bfloat16(v.y);
            d[2] = __float2bfloat16(v.z); d[3] = __float2bfloat16(v.w);
        }
    }

    {
        const int key0 = ks*KPB;
        const float4* srcK = (const float4*)(Kb + (size_t)key0*16);
        const float4* srcV = (const float4*)(Vb + (size_t)key0*16);
#pragma unroll
        for (int i = t; i < KT*4; i += 128) {
            float4 kv = srcK[i];
            int key = i >> 2, dq = (i & 3) * 4;
            __nv_bfloat16* d = sK[0] + key*SKQ + dq;
            d[0] = __float2bfloat16(kv.x); d[1] = __float2bfloat16(kv.y);
            d[2] = __float2bfloat16(kv.z); d[3] = __float2bfloat16(kv.w);
            float4 vv = srcV[i];
            sVt[0][(dq+0)*SVT + key] = __float2bfloat16(vv.x);
            sVt[0][(dq+1)*SVT + key] = __float2bfloat16(vv.y);
            sVt[0][(dq+2)*SVT + key] = __float2bfloat16(vv.z);
            sVt[0][(dq+3)*SVT + key] = __float2bfloat16(vv.w);
        }
    }
    __syncthreads();

    const int qr = wid * 16;
    uint32_t qa0 = *(const uint32_t*)(sQ + (qr+g  )*SKQ + 2*tg);
    uint32_t qa1 = *(const uint32_t*)(sQ + (qr+g+8)*SKQ + 2*tg);
    uint32_t qa2 = *(const uint32_t*)(sQ + (qr+g  )*SKQ + 2*tg + 8);
    uint32_t qa3 = *(const uint32_t*)(sQ + (qr+g+8)*SKQ + 2*tg + 8);

    float o[2][4] = {{0,0,0,0},{0,0,0,0}};
    float lsum_lo = 0.f, lsum_hi = 0.f;
    const float SC = 0.25f * 1.4426950408889634f;   // scale * log2(e)

    for (int kt = 0; kt < NTIL; kt++) {
        const int cur = kt & 1;
        const bool more = (kt + 1 < NTIL);

        float4 kreg[2], vreg[2];
        if (more) {
            const int key0 = ks*KPB + (kt+1)*KT;
            const float4* srcK = (const float4*)(Kb + (size_t)key0*16);
            const float4* srcV = (const float4*)(Vb + (size_t)key0*16);
#pragma unroll
            for (int u = 0; u < 2; u++) {
                kreg[u] = srcK[t + u*128];
                vreg[u] = srcV[t + u*128];
            }
        }

        const __nv_bfloat16* kb_s = sK[cur];
        const __nv_bfloat16* vb_s = sVt[cur];

        float s[8][4];
        uint32_t p[8][2];
#pragma unroll
        for (int n = 0; n < 8; n++) {
            s[n][0] = s[n][1] = s[n][2] = s[n][3] = 0.f;
            uint32_t b0 = *(const uint32_t*)(kb_s + (n*8+g)*SKQ + 2*tg);
            uint32_t b1 = *(const uint32_t*)(kb_s + (n*8+g)*SKQ + 2*tg + 8);
            mma16816(s[n], qa0, qa1, qa2, qa3, b0, b1);
        }
#pragma unroll
        for (int n = 0; n < 8; n++) {
            float e0 = ex2a(s[n][0]*SC), e1 = ex2a(s[n][1]*SC);
            float e2 = ex2a(s[n][2]*SC), e3 = ex2a(s[n][3]*SC);
            lsum_lo += e0 + e1;  lsum_hi += e2 + e3;
            p[n][0] = cvt_bf2(e1, e0);
            p[n][1] = cvt_bf2(e3, e2);
        }
#pragma unroll
        for (int kk = 0; kk < 4; kk++) {
            uint32_t a0 = p[2*kk][0],   a1 = p[2*kk][1];
            uint32_t a2 = p[2*kk+1][0], a3 = p[2*kk+1][1];
#pragma unroll
            for (int n = 0; n < 2; n++) {
                uint32_t b0 = *(const uint32_t*)(vb_s + (n*8+g)*SVT + kk*16 + 2*tg);
                uint32_t b1 = *(const uint32_t*)(vb_s + (n*8+g)*SVT + kk*16 + 2*tg + 8);
                mma16816(o[n], a0, a1, a2, a3, b0, b1);
            }
        }

        if (more) {
            const int nxt = cur ^ 1;
#pragma unroll
            for (int u = 0; u < 2; u++) {
                int i = t + u*128;
                int key = i >> 2, dq = (i & 3) * 4;
                __nv_bfloat16* d = sK[nxt] + key*SKQ + dq;
                d[0] = __float2bfloat16(kreg[u].x); d[1] = __float2bfloat16(kreg[u].y);
                d[2] = __float2bfloat16(kreg[u].z); d[3] = __float2bfloat16(kreg[u].w);
                sVt[nxt][(dq+0)*SVT + key] = __float2bfloat16(vreg[u].x);
                sVt[nxt][(dq+1)*SVT + key] = __float2bfloat16(vreg[u].y);
                sVt[nxt][(dq+2)*SVT + key] = __float2bfloat16(vreg[u].z);
                sVt[nxt][(dq+3)*SVT + key] = __float2bfloat16(vreg[u].w);
            }
            __syncthreads();
        }
    }

    lsum_lo += __shfl_xor_sync(0xffffffffu, lsum_lo, 1);
    lsum_lo += __shfl_xor_sync(0xffffffffu, lsum_lo, 2);
    lsum_hi += __shfl_xor_sync(0xffffffffu, lsum_hi, 1);
    lsum_hi += __shfl_xor_sync(0xffffffffu, lsum_hi, 2);

    const int q_lo = qt*QT + qr + g;
    const int q_hi = q_lo + 8;
    float* po = g_po + ((size_t)(ks*BH + bh)*Nn)*16;
#pragma unroll
    for (int n = 0; n < 2; n++) {
        po[(size_t)q_lo*16 + n*8 + 2*tg    ] = o[n][0];
        po[(size_t)q_lo*16 + n*8 + 2*tg + 1] = o[n][1];
        po[(size_t)q_hi*16 + n*8 + 2*tg    ] = o[n][2];
        po[(size_t)q_hi*16 + n*8 + 2*tg + 1] = o[n][3];
    }
    if (tg == 0) {
        g_pl[(size_t)(ks*BH + bh)*Nn + q_lo] = lsum_lo;
        g_pl[(size_t)(ks*BH + bh)*Nn + q_hi] = lsum_hi;
    }
}

// ---------------- K4: combine + epilogue + out-proj + LN2 + MLP (8 rows, 128 thr) ----------------
__device__ __forceinline__ float leaky(float h) { return h > 0.f ? h : 0.01f * h; }

__global__ __launch_bounds__(128) void k_tail(
    const float* __restrict__ wout, const float* __restrict__ bout,
    const float* __restrict__ g2,   const float* __restrict__ be2,
    const float* __restrict__ w1,   const float* __restrict__ b1,
    const float* __restrict__ w2,   const float* __restrict__ b2,
    float* __restrict__ out)
{
    const int t = threadIdx.x;
    const int c = t & 63, h2 = t >> 6;
    const int row0 = blockIdx.x * 8;
    const int b = row0 / Nn;
    const int n0 = row0 - b*Nn;
    const int h = c >> 4, d = c & 15;
    const int bh = b*Hh + h;

    __shared__ float ssec[4][256];
    __shared__ float sq[8][64];
    __shared__ float sinvl[8][4];
    __shared__ u64 sop[4][64];
    __shared__ u64 snp[4][64];
    __shared__ u64 shp[4][256];
    __shared__ float sred[4][8];

#pragma unroll
    for (int k = 0; k < 8; k++) {
        int idx = k*128 + t;
        ssec[idx >> 8][idx & 255] = g_secm[(b*Hh + (idx >> 8))*256 + (idx & 255)];
    }
#pragma unroll
    for (int k = 0; k < 4; k++)
        sq[4*h2 + k][c] = g_y1[((size_t)bh*Nn + n0 + 4*h2 + k)*16 + d];
    if (t < 32) {
        int r = t >> 2, hh = t & 3;
        float l = 0.f;
#pragma unroll
        for (int ks = 0; ks < KSPL; ks++)
            l += g_pl[(size_t)(ks*BH + b*Hh + hh)*Nn + n0 + r];
        sinvl[r][hh] = 1.0f / l;
    }
    __syncthreads();

    // combine splits + channel-map epilogue for own 4 rows
    float soval[4];
#pragma unroll
    for (int k = 0; k < 4; k++) {
        int r = 4*h2 + k;
        float pv = 0.f;
#pragma unroll
        for (int ks = 0; ks < KSPL; ks++)
            pv += g_po[((size_t)(ks*BH + bh)*Nn + n0 + r)*16 + d];
        float o2 = 0.f;
#pragma unroll
        for (int i = 0; i < 16; i++)
            o2 = fmaf(sq[r][h*16 + i], ssec[h][i*16 + d], o2);
        soval[k] = pv * sinvl[r][h] * o2;
    }
    sop[2*h2  ][c] = pk(soval[0], soval[1]);
    sop[2*h2+1][c] = pk(soval[2], soval[3]);
    __syncthreads();

    // out-proj for own 2 pairs
    u64 ac[2] = {0ull, 0ull};
#pragma unroll 4
    for (int c2 = 0; c2 < 64; c2++) {
        float w = wout[c2*64 + c];
        u64 ww = pk(w, w);
        ac[0] = fma2(ww, sop[2*h2  ][c2], ac[0]);
        ac[1] = fma2(ww, sop[2*h2+1][c2], ac[1]);
    }
    const float bo = bout[c];
    float x2v[4];
#pragma unroll
    for (int pi = 0; pi < 2; pi++) {
        float2 u = unpk(ac[pi]);
        x2v[2*pi]   = g_xt[(size_t)(row0 + 4*h2 + 2*pi    )*64 + c] + u.x + bo;
        x2v[2*pi+1] = g_xt[(size_t)(row0 + 4*h2 + 2*pi + 1)*64 + c] + u.y + bo;
    }

    // LN2 for own 4 rows (reduce across this half's 2 warps)
    const int wid = t >> 5, lane = t & 31;
#pragma unroll
    for (int k = 0; k < 4; k++) {
        float a = x2v[k], a2 = a*a;
#pragma unroll
        for (int o = 16; o > 0; o >>= 1) {
            a  += __shfl_xor_sync(0xffffffffu, a,  o);
            a2 += __shfl_xor_sync(0xffffffffu, a2, o);
        }
        if (lane == 0) { sred[wid][k*2] = a; sred[wid][k*2+1] = a2; }
    }
    __syncthreads();
    const float g2t = g2[c], be2t = be2[c];
    const int wA = 2*h2, wB = 2*h2 + 1;
    float snv[4];
#pragma unroll
    for (int k = 0; k < 4; k++) {
        float sxx = sred[wA][k*2]   + sred[wB][k*2];
        float sq2 = sred[wA][k*2+1] + sred[wB][k*2+1];
        float m = sxx*(1.f/64.f), v = sq2*(1.f/64.f) - m*m;
        snv[k] = (x2v[k]-m)*rsqrtf(v + 1e-5f)*g2t + be2t;
    }
    snp[2*h2  ][c] = pk(snv[0], snv[1]);
    snp[2*h2+1][c] = pk(snv[2], snv[3]);
    __syncthreads();

    // MLP layer 1 (64->256): this thread owns outputs c+64*(h2+2*kk), kk=0,1,
    // for ALL 4 row-pairs.
    u64 hh1[2][4];
#pragma unroll
    for (int kk = 0; kk < 2; kk++) {
        float bb = b1[c + 64*(h2 + 2*kk)];
#pragma unroll
        for (int p = 0; p < 4; p++) hh1[kk][p] = pk(bb, bb);
    }
#pragma unroll 2
    for (int c2 = 0; c2 < 64; c2++) {
        u64 xp[4];
#pragma unroll
        for (int p = 0; p < 4; p++) xp[p] = snp[p][c2];
#pragma unroll
        for (int kk = 0; kk < 2; kk++) {
            float w = w1[c2*256 + c + 64*(h2 + 2*kk)];
            u64 ww = pk(w, w);
#pragma unroll
            for (int p = 0; p < 4; p++)
                hh1[kk][p] = fma2(ww, xp[p], hh1[kk][p]);
        }
    }
#pragma unroll
    for (int kk = 0; kk < 2; kk++) {
#pragma unroll
        for (int p = 0; p < 4; p++) {
            float2 u = unpk(hh1[kk][p]);
            shp[p][c + 64*(h2 + 2*kk)] = pk(leaky(u.x), leaky(u.y));
        }
    }
    __syncthreads();

    // MLP layer 2 (256->64) for own 2 pairs
    u64 f[2] = {0ull, 0ull};
#pragma unroll 4
    for (int j = 0; j < 256; j++) {
        float w = w2[j*64 + c];
        u64 ww = pk(w, w);
        f[0] = fma2(ww, shp[2*h2  ][j], f[0]);
        f[1] = fma2(ww, shp[2*h2+1][j], f[1]);
    }
    const float b2t = b2[c];
#pragma unroll
    for (int pi = 0; pi < 2; pi++) {
        float2 u = unpk(f[pi]);
        out[((size_t)b*Cc + c)*Nn + n0 + 4*h2 + 2*pi    ] = x2v[2*pi]   + u.x + b2t;
        out[((size_t)b*Cc + c)*Nn + n0 + 4*h2 + 2*pi + 1] = x2v[2*pi+1] + u.y + b2t;
    }
}

// ---------------- launch ----------------
extern "C" void kernel_launch(void* const* d_in, const int* in_sizes, int n_in,
                              void* d_out, int out_size)
{
    (void)in_sizes; (void)n_in; (void)out_size;
    const float* x    = (const float*)d_in[0];
    const float* y    = (const float*)d_in[1];
    const float* ln1g = (const float*)d_in[2];
    const float* ln1b = (const float*)d_in[3];
    const float* wsa1 = (const float*)d_in[4];
    const float* wsa2 = (const float*)d_in[5];
    const float* wse1 = (const float*)d_in[6];
    const float* wse2 = (const float*)d_in[7];
    const float* wout = (const float*)d_in[8];
    const float* bout = (const float*)d_in[9];
    const float* ln2g = (const float*)d_in[10];
    const float* ln2b = (const float*)d_in[11];
    const float* w1   = (const float*)d_in[12];
    const float* b1   = (const float*)d_in[13];
    const float* w2   = (const float*)d_in[14];
    const float* b2   = (const float*)d_in[15];
    float* out = (float*)d_out;

    k_ln_proj<<<Bb*Nn/8, 128>>>(x, y, ln1g, ln1b, wsa1, wsa2, wse1, wse2);
    dim3 gsec(NTILE, BH);
    k_secm_part<<<gsec, 256>>>();
    k_secm_soft<<<BH, 256>>>();
    dim3 gfl(Nn/QT, BH, KSPL);
    k_flash_mma<<<gfl, 128>>>();
    k_tail<<<Bb*Nn/8, 128>>>(wout, bout, ln2g, ln2b, w1, b1, w2, b2, out);
}

// round 8
// speedup vs baseline: 1.3228x; 1.2355x over previous
#include <cuda_runtime.h>
#include <cuda_bf16.h>
#include <cstdint>

#define Bb   2
#define Cc   64
#define Nn   2304
#define Hh   4
#define Dh   16
#define BH   (Bb*Hh)
#define MLP  256

// flash-mma tiling
#define QT    64            // queries per block (4 warps x 16 rows)
#define KT    64            // keys per smem tile
#define KSPL  4             // key splits
#define KPB   (Nn/KSPL)     // 576 keys per block
#define NTIL  (KPB/KT)      // 9 tiles
#define SKQ   24            // row stride in bf16 (48B = 3*16B, ldmatrix-friendly)

typedef unsigned long long u64;

// ---------------- scratch (device globals; no allocation) ----------------
__device__ float g_xt [Bb*Nn*Cc];
__device__ float g_y1 [BH*Nn*Dh];
__device__ float g_y2 [BH*Nn*Dh];
__device__ float g_x1 [BH*Nn*Dh];
__device__ float g_secl[BH*256];         // channel-attn logits (atomic accum)
__device__ float g_po [KSPL*BH*Nn*16];   // unnormalized attention partials
__device__ float g_pl [KSPL*BH*Nn];      // partial row sums

// ---------------- helpers ----------------
__device__ __forceinline__ float ex2a(float x) {
    float r; asm("ex2.approx.f32 %0, %1;" : "=f"(r) : "f"(x)); return r;
}
__device__ __forceinline__ uint32_t cvt_bf2(float hi, float lo) {
    uint32_t r; asm("cvt.rn.bf16x2.f32 %0, %1, %2;" : "=r"(r) : "f"(hi), "f"(lo)); return r;
}
__device__ __forceinline__ void mma16816(float d[4],
    uint32_t a0, uint32_t a1, uint32_t a2, uint32_t a3,
    uint32_t b0, uint32_t b1)
{
    asm volatile("mma.sync.aligned.m16n8k16.row.col.f32.bf16.bf16.f32 "
        "{%0,%1,%2,%3}, {%4,%5,%6,%7}, {%8,%9}, {%0,%1,%2,%3};"
        : "+f"(d[0]), "+f"(d[1]), "+f"(d[2]), "+f"(d[3])
        : "r"(a0), "r"(a1), "r"(a2), "r"(a3), "r"(b0), "r"(b1));
}
__device__ __forceinline__ void ldsm_x4(uint32_t& r0, uint32_t& r1, uint32_t& r2, uint32_t& r3, uint32_t addr) {
    asm volatile("ldmatrix.sync.aligned.m8n8.x4.shared.b16 {%0,%1,%2,%3}, [%4];"
        : "=r"(r0), "=r"(r1), "=r"(r2), "=r"(r3) : "r"(addr));
}
__device__ __forceinline__ void ldsm_x4t(uint32_t& r0, uint32_t& r1, uint32_t& r2, uint32_t& r3, uint32_t addr) {
    asm volatile("ldmatrix.sync.aligned.m8n8.x4.trans.shared.b16 {%0,%1,%2,%3}, [%4];"
        : "=r"(r0), "=r"(r1), "=r"(r2), "=r"(r3) : "r"(addr));
}
__device__ __forceinline__ u64 fma2(u64 a, u64 b, u64 c) {
    u64 d; asm("fma.rn.f32x2 %0, %1, %2, %3;" : "=l"(d) : "l"(a), "l"(b), "l"(c)); return d;
}
__device__ __forceinline__ float2 unpk(u64 v) {
    float2 r; asm("mov.b64 {%0,%1}, %2;" : "=f"(r.x), "=f"(r.y) : "l"(v)); return r;
}
__device__ __forceinline__ u64 pk(float lo, float hi) {
    u64 v; asm("mov.b64 %0, {%1,%2};" : "=l"(v) : "f"(lo), "f"(hi)); return v;
}
__device__ __forceinline__ uint32_t smem_u32(const void* p) {
    return (uint32_t)__cvta_generic_to_shared(p);
}

// ---------------- K1: transpose + LN + 4 projections + secm partials ----------------
// 8 rows, 128 thr. Half h2 = t>>6 owns rows 4*h2..4*h2+3.
__global__ __launch_bounds__(128) void k_ln_proj(
    const float* __restrict__ x, const float* __restrict__ y,
    const float* __restrict__ g, const float* __restrict__ be,
    const float* __restrict__ wsa1, const float* __restrict__ wsa2,
    const float* __restrict__ wse1, const float* __restrict__ wse2)
{
    const int t = threadIdx.x;
    const int c = t & 63, h2 = t >> 6;
    const int row0 = blockIdx.x * 8;
    const int b = row0 / Nn;
    const int n0 = row0 - b*Nn;
    __shared__ u64 sxnp[4][64], synp[4][64];
    __shared__ u64 sx1p[4][64], sx2p[4][64];
    __shared__ float sred[4][16];

    float xv[4], yv[4];
#pragma unroll
    for (int k = 0; k < 4; k++) {
        int nn = n0 + 4*h2 + k;
        xv[k] = x[((size_t)b*Cc + c)*Nn + nn];
        yv[k] = y[((size_t)b*Cc + c)*Nn + nn];
        g_xt[(size_t)(row0 + 4*h2 + k)*Cc + c] = xv[k];
    }
    const int wid = t >> 5, lane = t & 31;
#pragma unroll
    for (int k = 0; k < 4; k++) {
        float a = xv[k], a2 = a*a, bb = yv[k], b2v = bb*bb;
#pragma unroll
        for (int o = 16; o > 0; o >>= 1) {
            a   += __shfl_xor_sync(0xffffffffu, a,   o);
            a2  += __shfl_xor_sync(0xffffffffu, a2,  o);
            bb  += __shfl_xor_sync(0xffffffffu, bb,  o);
            b2v += __shfl_xor_sync(0xffffffffu, b2v, o);
        }
        if (lane == 0) {
            sred[wid][k*4+0] = a;  sred[wid][k*4+1] = a2;
            sred[wid][k*4+2] = bb; sred[wid][k*4+3] = b2v;
        }
    }
    __syncthreads();
    const float gt = g[c], bet = be[c];
    float xnv[4], ynv[4];
    const int w0i = 2*h2, w1i = 2*h2 + 1;
#pragma unroll
    for (int k = 0; k < 4; k++) {
        float sx  = sred[w0i][k*4+0] + sred[w1i][k*4+0];
        float sx2 = sred[w0i][k*4+1] + sred[w1i][k*4+1];
        float sy  = sred[w0i][k*4+2] + sred[w1i][k*4+2];
        float sy2 = sred[w0i][k*4+3] + sred[w1i][k*4+3];
        float mx = sx*(1.f/64.f), vx = sx2*(1.f/64.f) - mx*mx;
        float my = sy*(1.f/64.f), vy = sy2*(1.f/64.f) - my*my;
        float rx = rsqrtf(vx + 1e-5f), ry = rsqrtf(vy + 1e-5f);
        xnv[k] = (xv[k]-mx)*rx*gt + bet;
        ynv[k] = (yv[k]-my)*ry*gt + bet;
    }
    sxnp[2*h2  ][c] = pk(xnv[0], xnv[1]);
    sxnp[2*h2+1][c] = pk(xnv[2], xnv[3]);
    synp[2*h2  ][c] = pk(ynv[0], ynv[1]);
    synp[2*h2+1][c] = pk(ynv[2], ynv[3]);
    __syncthreads();

    u64 a1[2] = {0,0}, a2a[2] = {0,0}, a3[2] = {0,0}, a4[2] = {0,0};
#pragma unroll 4
    for (int c2 = 0; c2 < 64; c2++) {
        float w1v = wsa1[c2*64+c], w2v = wsa2[c2*64+c];
        float w3v = wse1[c2*64+c], w4v = wse2[c2*64+c];
        u64 w1p = pk(w1v, w1v), w2p = pk(w2v, w2v);
        u64 w3p = pk(w3v, w3v), w4p = pk(w4v, w4v);
#pragma unroll
        for (int pi = 0; pi < 2; pi++) {
            u64 yc = synp[2*h2+pi][c2], xc = sxnp[2*h2+pi][c2];
            a1[pi]  = fma2(yc, w1p, a1[pi]);
            a2a[pi] = fma2(yc, w2p, a2a[pi]);
            a3[pi]  = fma2(xc, w3p, a3[pi]);
            a4[pi]  = fma2(xc, w4p, a4[pi]);
        }
    }
    const int h = c >> 4, d = c & 15;
#pragma unroll
    for (int pi = 0; pi < 2; pi++) {
        size_t o0 = ((size_t)(b*Hh + h)*Nn + n0 + 4*h2 + 2*pi)*Dh + d;
        size_t o1 = o0 + Dh;
        float2 u1 = unpk(a1[pi]),  u2 = unpk(a2a[pi]);
        float2 u3 = unpk(a3[pi]);
        g_y1[o0] = u1.x; g_y1[o1] = u1.y;
        g_y2[o0] = u2.x; g_y2[o1] = u2.y;
        g_x1[o0] = u3.x; g_x1[o1] = u3.y;
    }

    // ---- channel-attn logit partials: sum over the 8 rows, atomic into g_secl
    sx1p[2*h2  ][c] = a3[0];  sx1p[2*h2+1][c] = a3[1];
    sx2p[2*h2  ][c] = a4[0];  sx2p[2*h2+1][c] = a4[1];
    __syncthreads();
#pragma unroll
    for (int e = 0; e < 8; e++) {
        int idx = t + 128*e;
        int hh = idx >> 8, ii = (idx >> 4) & 15, jj = idx & 15;
        u64 acc = 0ull;
#pragma unroll
        for (int p = 0; p < 4; p++)
            acc = fma2(sx1p[p][hh*16+ii], sx2p[p][hh*16+jj], acc);
        float2 u = unpk(acc);
        atomicAdd(&g_secl[(b*Hh + hh)*256 + ii*16 + jj], u.x + u.y);
    }
}

// ---------------- K3: flash attention, bf16 mma + ldmatrix, double-buffered ----------------
__global__ __launch_bounds__(128) void k_flash_mma()
{
    const int qt = blockIdx.x, bh = blockIdx.y, ks = blockIdx.z;
    const int t = threadIdx.x, wid = t >> 5, lane = t & 31;
    const int g = lane >> 2, tg = lane & 3;
    const int m = lane >> 3, r8 = lane & 7;

    __shared__ __align__(16) __nv_bfloat16 sQ [QT*SKQ];
    __shared__ __align__(16) __nv_bfloat16 sK [2][KT*SKQ];
    __shared__ __align__(16) __nv_bfloat16 sV [2][KT*SKQ];

    const float* __restrict__ Qb = g_y1 + (size_t)bh*Nn*Dh;
    const float* __restrict__ Kb = g_y2 + (size_t)bh*Nn*Dh;
    const float* __restrict__ Vb = g_x1 + (size_t)bh*Nn*Dh;

    // Q tile -> bf16 smem (packed 8B stores)
    {
        const float4* src = (const float4*)(Qb + (size_t)qt*QT*16);
#pragma unroll
        for (int i = t; i < QT*4; i += 128) {
            float4 v = src[i];
            int key = i >> 2, dq = (i & 3) * 4;
            uint32_t lo = cvt_bf2(v.y, v.x), hi = cvt_bf2(v.w, v.z);
            *(uint2*)(sQ + key*SKQ + dq) = make_uint2(lo, hi);
        }
    }
    // preload tile 0
    {
        const int key0 = ks*KPB;
        const float4* srcK = (const float4*)(Kb + (size_t)key0*16);
        const float4* srcV = (const float4*)(Vb + (size_t)key0*16);
#pragma unroll
        for (int i = t; i < KT*4; i += 128) {
            int key = i >> 2, dq = (i & 3) * 4;
            float4 kv = srcK[i];
            *(uint2*)(sK[0] + key*SKQ + dq) = make_uint2(cvt_bf2(kv.y, kv.x), cvt_bf2(kv.w, kv.z));
            float4 vv = srcV[i];
            *(uint2*)(sV[0] + key*SKQ + dq) = make_uint2(cvt_bf2(vv.y, vv.x), cvt_bf2(vv.w, vv.z));
        }
    }
    __syncthreads();

    const int qr = wid * 16;
    uint32_t qa0 = *(const uint32_t*)(sQ + (qr+g  )*SKQ + 2*tg);
    uint32_t qa1 = *(const uint32_t*)(sQ + (qr+g+8)*SKQ + 2*tg);
    uint32_t qa2 = *(const uint32_t*)(sQ + (qr+g  )*SKQ + 2*tg + 8);
    uint32_t qa3 = *(const uint32_t*)(sQ + (qr+g+8)*SKQ + 2*tg + 8);

    // per-lane ldmatrix byte offsets within a 64x24(bf16) buffer
    // K (B=K^T, non-trans): m0=(keys0-7,d0-7) m1=(keys0-7,d8-15) m2=(+8,d0-7) m3=(+8,d8-15)
    const uint32_t offK = (uint32_t)(((((m>>1)&1)*8 + r8)*SKQ + (m&1)*8) * 2);
    // V (B=V, trans): m0=(k0-7,d0-7) m1=(k8-15,d0-7) m2=(k0-7,d8-15) m3=(k8-15,d8-15)
    const uint32_t offV = (uint32_t)((((m&1)*8 + r8)*SKQ + ((m>>1)&1)*8) * 2);
    const uint32_t kb0 = smem_u32(sK[0]), kb1 = smem_u32(sK[1]);
    const uint32_t vb0 = smem_u32(sV[0]), vb1 = smem_u32(sV[1]);

    float o[2][4] = {{0,0,0,0},{0,0,0,0}};
    float lsum_lo = 0.f, lsum_hi = 0.f;
    const float SC = 0.25f * 1.4426950408889634f;

    for (int kt = 0; kt < NTIL; kt++) {
        const int cur = kt & 1;
        const bool more = (kt + 1 < NTIL);

        float4 kreg[2], vreg[2];
        if (more) {
            const int key0 = ks*KPB + (kt+1)*KT;
            const float4* srcK = (const float4*)(Kb + (size_t)key0*16);
            const float4* srcV = (const float4*)(Vb + (size_t)key0*16);
#pragma unroll
            for (int u = 0; u < 2; u++) {
                kreg[u] = srcK[t + u*128];
                vreg[u] = srcV[t + u*128];
            }
        }

        const uint32_t kbase = (cur ? kb1 : kb0) + offK;
        const uint32_t vbase = (cur ? vb1 : vb0) + offV;

        float s[8][4];
        uint32_t p[8][2];
#pragma unroll
        for (int kg = 0; kg < 4; kg++) {
            uint32_t b0, b1, b2, b3;
            ldsm_x4(b0, b1, b2, b3, kbase + kg*(16*SKQ*2));
            s[2*kg][0] = s[2*kg][1] = s[2*kg][2] = s[2*kg][3] = 0.f;
            s[2*kg+1][0] = s[2*kg+1][1] = s[2*kg+1][2] = s[2*kg+1][3] = 0.f;
            mma16816(s[2*kg],   qa0, qa1, qa2, qa3, b0, b1);
            mma16816(s[2*kg+1], qa0, qa1, qa2, qa3, b2, b3);
        }
#pragma unroll
        for (int n = 0; n < 8; n++) {
            float e0 = ex2a(s[n][0]*SC), e1 = ex2a(s[n][1]*SC);
            float e2 = ex2a(s[n][2]*SC), e3 = ex2a(s[n][3]*SC);
            lsum_lo += e0 + e1;  lsum_hi += e2 + e3;
            p[n][0] = cvt_bf2(e1, e0);
            p[n][1] = cvt_bf2(e3, e2);
        }
#pragma unroll
        for (int kk = 0; kk < 4; kk++) {
            uint32_t v0, v1, v2, v3;
            ldsm_x4t(v0, v1, v2, v3, vbase + kk*(16*SKQ*2));
            mma16816(o[0], p[2*kk][0], p[2*kk][1], p[2*kk+1][0], p[2*kk+1][1], v0, v1);
            mma16816(o[1], p[2*kk][0], p[2*kk][1], p[2*kk+1][0], p[2*kk+1][1], v2, v3);
        }

        if (more) {
            const int nxt = cur ^ 1;
#pragma unroll
            for (int u = 0; u < 2; u++) {
                int i = t + u*128;
                int key = i >> 2, dq = (i & 3) * 4;
                *(uint2*)(sK[nxt] + key*SKQ + dq) =
                    make_uint2(cvt_bf2(kreg[u].y, kreg[u].x), cvt_bf2(kreg[u].w, kreg[u].z));
                *(uint2*)(sV[nxt] + key*SKQ + dq) =
                    make_uint2(cvt_bf2(vreg[u].y, vreg[u].x), cvt_bf2(vreg[u].w, vreg[u].z));
            }
            __syncthreads();
        }
    }

    lsum_lo += __shfl_xor_sync(0xffffffffu, lsum_lo, 1);
    lsum_lo += __shfl_xor_sync(0xffffffffu, lsum_lo, 2);
    lsum_hi += __shfl_xor_sync(0xffffffffu, lsum_hi, 1);
    lsum_hi += __shfl_xor_sync(0xffffffffu, lsum_hi, 2);

    const int q_lo = qt*QT + qr + g;
    const int q_hi = q_lo + 8;
    float* po = g_po + ((size_t)(ks*BH + bh)*Nn)*16;
#pragma unroll
    for (int n = 0; n < 2; n++) {
        po[(size_t)q_lo*16 + n*8 + 2*tg    ] = o[n][0];
        po[(size_t)q_lo*16 + n*8 + 2*tg + 1] = o[n][1];
        po[(size_t)q_hi*16 + n*8 + 2*tg    ] = o[n][2];
        po[(size_t)q_hi*16 + n*8 + 2*tg + 1] = o[n][3];
    }
    if (tg == 0) {
        g_pl[(size_t)(ks*BH + bh)*Nn + q_lo] = lsum_lo;
        g_pl[(size_t)(ks*BH + bh)*Nn + q_hi] = lsum_hi;
    }
}

// ---------------- K4: secm softmax + combine + epilogue + out-proj + LN2 + MLP ----------------
__device__ __forceinline__ float leaky(float h) { return h > 0.f ? h : 0.01f * h; }

__global__ __launch_bounds__(128) void k_tail(
    const float* __restrict__ wout, const float* __restrict__ bout,
    const float* __restrict__ g2,   const float* __restrict__ be2,
    const float* __restrict__ w1,   const float* __restrict__ b1,
    const float* __restrict__ w2,   const float* __restrict__ b2,
    float* __restrict__ out)
{
    const int t = threadIdx.x;
    const int c = t & 63, h2 = t >> 6;
    const int row0 = blockIdx.x * 8;
    const int b = row0 / Nn;
    const int n0 = row0 - b*Nn;
    const int h = c >> 4, d = c & 15;
    const int bh = b*Hh + h;

    __shared__ float ssec[4][256];
    __shared__ float sq[8][64];
    __shared__ float sinvl[8][4];
    __shared__ u64 sop[4][64];
    __shared__ u64 snp[4][64];
    __shared__ u64 shp[4][256];
    __shared__ float sred[4][8];

    // channel-attn softmax from logit accumulator
    const float SCL = 0.25f / 144.0f;
#pragma unroll
    for (int k = 0; k < 8; k++) {
        int idx = k*128 + t;
        ssec[idx >> 8][idx & 255] = g_secl[(b*Hh + (idx >> 8))*256 + (idx & 255)];
    }
#pragma unroll
    for (int k = 0; k < 4; k++)
        sq[4*h2 + k][c] = g_y1[((size_t)bh*Nn + n0 + 4*h2 + k)*16 + d];
    if (t < 32) {
        int r = t >> 2, hh = t & 3;
        float l = 0.f;
#pragma unroll
        for (int ks = 0; ks < KSPL; ks++)
            l += g_pl[(size_t)(ks*BH + b*Hh + hh)*Nn + n0 + r];
        sinvl[r][hh] = 1.0f / l;
    }
    __syncthreads();
    if (t < 64) {
        int hh = t >> 4, ii = t & 15;
        float* row = &ssec[hh][ii*16];
        float rm = -1e30f;
#pragma unroll
        for (int j = 0; j < 16; j++) rm = fmaxf(rm, row[j]*SCL);
        float rs = 0.f;
        float ev[16];
#pragma unroll
        for (int j = 0; j < 16; j++) { ev[j] = __expf(row[j]*SCL - rm); rs += ev[j]; }
        float inv = 1.0f / rs;
#pragma unroll
        for (int j = 0; j < 16; j++) row[j] = ev[j] * inv;
    }
    __syncthreads();

    // combine splits + channel-map epilogue for own 4 rows
    float soval[4];
#pragma unroll
    for (int k = 0; k < 4; k++) {
        int r = 4*h2 + k;
        float pv = 0.f;
#pragma unroll
        for (int ks = 0; ks < KSPL; ks++)
            pv += g_po[((size_t)(ks*BH + bh)*Nn + n0 + r)*16 + d];
        float o2 = 0.f;
#pragma unroll
        for (int i = 0; i < 16; i++)
            o2 = fmaf(sq[r][h*16 + i], ssec[h][i*16 + d], o2);
        soval[k] = pv * sinvl[r][h] * o2;
    }
    sop[2*h2  ][c] = pk(soval[0], soval[1]);
    sop[2*h2+1][c] = pk(soval[2], soval[3]);
    __syncthreads();

    u64 ac[2] = {0ull, 0ull};
#pragma unroll 4
    for (int c2 = 0; c2 < 64; c2++) {
        float w = wout[c2*64 + c];
        u64 ww = pk(w, w);
        ac[0] = fma2(ww, sop[2*h2  ][c2], ac[0]);
        ac[1] = fma2(ww, sop[2*h2+1][c2], ac[1]);
    }
    const float bo = bout[c];
    float x2v[4];
#pragma unroll
    for (int pi = 0; pi < 2; pi++) {
        float2 u = unpk(ac[pi]);
        x2v[2*pi]   = g_xt[(size_t)(row0 + 4*h2 + 2*pi    )*64 + c] + u.x + bo;
        x2v[2*pi+1] = g_xt[(size_t)(row0 + 4*h2 + 2*pi + 1)*64 + c] + u.y + bo;
    }

    const int wid = t >> 5, lane = t & 31;
#pragma unroll
    for (int k = 0; k < 4; k++) {
        float a = x2v[k], a2 = a*a;
#pragma unroll
        for (int o = 16; o > 0; o >>= 1) {
            a  += __shfl_xor_sync(0xffffffffu, a,  o);
            a2 += __shfl_xor_sync(0xffffffffu, a2, o);
        }
        if (lane == 0) { sred[wid][k*2] = a; sred[wid][k*2+1] = a2; }
    }
    __syncthreads();
    const float g2t = g2[c], be2t = be2[c];
    const int wA = 2*h2, wB = 2*h2 + 1;
    float snv[4];
#pragma unroll
    for (int k = 0; k < 4; k++) {
        float sxx = sred[wA][k*2]   + sred[wB][k*2];
        float sq2 = sred[wA][k*2+1] + sred[wB][k*2+1];
        float mm = sxx*(1.f/64.f), vv = sq2*(1.f/64.f) - mm*mm;
        snv[k] = (x2v[k]-mm)*rsqrtf(vv + 1e-5f)*g2t + be2t;
    }
    snp[2*h2  ][c] = pk(snv[0], snv[1]);
    snp[2*h2+1][c] = pk(snv[2], snv[3]);
    __syncthreads();

    u64 hh1[2][4];
#pragma unroll
    for (int kk = 0; kk < 2; kk++) {
        float bb = b1[c + 64*(h2 + 2*kk)];
#pragma unroll
        for (int p = 0; p < 4; p++) hh1[kk][p] = pk(bb, bb);
    }
#pragma unroll 2
    for (int c2 = 0; c2 < 64; c2++) {
        u64 xp[4];
#pragma unroll
        for (int p = 0; p < 4; p++) xp[p] = snp[p][c2];
#pragma unroll
        for (int kk = 0; kk < 2; kk++) {
            float w = w1[c2*256 + c + 64*(h2 + 2*kk)];
            u64 ww = pk(w, w);
#pragma unroll
            for (int p = 0; p < 4; p++)
                hh1[kk][p] = fma2(ww, xp[p], hh1[kk][p]);
        }
    }
#pragma unroll
    for (int kk = 0; kk < 2; kk++) {
#pragma unroll
        for (int p = 0; p < 4; p++) {
            float2 u = unpk(hh1[kk][p]);
            shp[p][c + 64*(h2 + 2*kk)] = pk(leaky(u.x), leaky(u.y));
        }
    }
    __syncthreads();

    u64 f[2] = {0ull, 0ull};
#pragma unroll 4
    for (int j = 0; j < 256; j++) {
        float w = w2[j*64 + c];
        u64 ww = pk(w, w);
        f[0] = fma2(ww, shp[2*h2  ][j], f[0]);
        f[1] = fma2(ww, shp[2*h2+1][j], f[1]);
    }
    const float b2t = b2[c];
#pragma unroll
    for (int pi = 0; pi < 2; pi++) {
        float2 u = unpk(f[pi]);
        out[((size_t)b*Cc + c)*Nn + n0 + 4*h2 + 2*pi    ] = x2v[2*pi]   + u.x + b2t;
        out[((size_t)b*Cc + c)*Nn + n0 + 4*h2 + 2*pi + 1] = x2v[2*pi+1] + u.y + b2t;
    }
}

// ---------------- launch ----------------
extern "C" void kernel_launch(void* const* d_in, const int* in_sizes, int n_in,
                              void* d_out, int out_size)
{
    (void)in_sizes; (void)n_in; (void)out_size;
    const float* x    = (const float*)d_in[0];
    const float* y    = (const float*)d_in[1];
    const float* ln1g = (const float*)d_in[2];
    const float* ln1b = (const float*)d_in[3];
    const float* wsa1 = (const float*)d_in[4];
    const float* wsa2 = (const float*)d_in[5];
    const float* wse1 = (const float*)d_in[6];
    const float* wse2 = (const float*)d_in[7];
    const float* wout = (const float*)d_in[8];
    const float* bout = (const float*)d_in[9];
    const float* ln2g = (const float*)d_in[10];
    const float* ln2b = (const float*)d_in[11];
    const float* w1   = (const float*)d_in[12];
    const float* b1   = (const float*)d_in[13];
    const float* w2   = (const float*)d_in[14];
    const float* b2   = (const float*)d_in[15];
    float* out = (float*)d_out;

    void* secl_ptr = nullptr;
    cudaGetSymbolAddress(&secl_ptr, g_secl);
    cudaMemsetAsync(secl_ptr, 0, BH*256*sizeof(float));

    k_ln_proj<<<Bb*Nn/8, 128>>>(x, y, ln1g, ln1b, wsa1, wsa2, wse1, wse2);
    dim3 gfl(Nn/QT, BH, KSPL);
    k_flash_mma<<<gfl, 128>>>();
    k_tail<<<Bb*Nn/8, 128>>>(wout, bout, ln2g, ln2b, w1, b1, w2, b2, out);
}